// round 11
// baseline (speedup 1.0000x reference)
#include <cuda_runtime.h>
#include <math.h>
#include <cstdint>

// FINAL: Output = 2*PE broadcast: 65536x64x16 fp32 = 256 MB of pure stores.
// Measured limiter (R1-R8): LTS chip store throughput ~6 TB/s, path-
// independent. STG.128 / STG.256 / TMA-bulk / dual-engine hybrids /
// L2-residency hints all land in the same 45.1-46.2 us band; cutting DRAM
// writeback 20% (R7) changed wall time by zero. This is the best-measured
// kernel (45.12 us): stage one 32 KB repetition of the 4 KB-periodic pattern
// in smem, then 1024 CTAs each issue exactly 8 cp.async.bulk 32 KB stores.

#define CHUNK_BYTES   32768        // 8 pattern periods; 16B-aligned
#define CHUNK_FLOAT4  (CHUNK_BYTES / 16)   // 2048

__global__ void __launch_bounds__(256)
pe_tma_store_kernel(float* __restrict__ out, long long n_chunks) {
    __shared__ __align__(128) float4 smem[CHUNK_FLOAT4];   // 32 KB static

    const int t = threadIdx.x;      // float4 index within the 256-float4 period
    const int pos = t >> 2;         // seq position 0..63
    const int c0  = (t & 3) * 4;    // first of 4 channels

    // Compute this thread's float4 of the pattern once.
    float4 v;
    {
        const float ln1e4_over8 = 1.1512925464970229f;  // ln(10000)/8
        float vals[4];
        #pragma unroll
        for (int k = 0; k < 4; ++k) {
            int c = c0 + k;
            float div = (float)pos * expf(-(float)c * ln1e4_over8);
            float s, co;
            sincosf(div, &s, &co);
            vals[k] = 2.0f * ((c & 1) == 0 ? s : co);
        }
        v.x = vals[0]; v.y = vals[1]; v.z = vals[2]; v.w = vals[3];
    }

    // Replicate pattern 8x into smem (32 KB).
    #pragma unroll
    for (int p = 0; p < 8; ++p)
        smem[p * 256 + t] = v;

    __syncthreads();

    // Order generic-proxy smem writes before async-proxy bulk reads.
    if (t == 0) {
        asm volatile("fence.proxy.async.shared::cta;" ::: "memory");

        uint32_t s_addr;
        asm("{ .reg .u64 a; cvta.to.shared.u64 a, %1; cvt.u32.u64 %0, a; }"
            : "=r"(s_addr) : "l"(smem));

        // Chunk-stride loop: CTA b handles chunks b, b+grid, ... (8 each).
        for (long long c = blockIdx.x; c < n_chunks; c += gridDim.x) {
            const char* dst = (const char*)out + c * (long long)CHUNK_BYTES;
            asm volatile(
                "cp.async.bulk.global.shared::cta.bulk_group [%0], [%1], %2;"
                :: "l"(dst), "r"(s_addr), "n"(CHUNK_BYTES) : "memory");
        }
        asm volatile("cp.async.bulk.commit_group;" ::: "memory");
        asm volatile("cp.async.bulk.wait_group 0;" ::: "memory");
    }
}

// Fallback tail writer (not expected to run for this shape).
__global__ void pe_tail_kernel(float* __restrict__ out,
                               long long start_f, long long total_f) {
    long long i = start_f + blockIdx.x * 256LL + threadIdx.x;
    if (i >= total_f) return;
    const float ln1e4_over8 = 1.1512925464970229f;
    int r = (int)(i & 1023);        // position within 1024-float period
    int pos = r >> 4;
    int c = r & 15;
    float div = (float)pos * expf(-(float)c * ln1e4_over8);
    float s, co;
    sincosf(div, &s, &co);
    out[i] = 2.0f * ((c & 1) == 0 ? s : co);
}

extern "C" void kernel_launch(void* const* d_in, const int* in_sizes, int n_in,
                              void* d_out, int out_size) {
    (void)d_in; (void)in_sizes; (void)n_in;
    long long total_bytes = (long long)out_size * 4;
    long long n_chunks = total_bytes / CHUNK_BYTES;          // 8192 for 256 MB
    long long rem_bytes = total_bytes - n_chunks * CHUNK_BYTES;

    if (n_chunks > 0) {
        int grid = (n_chunks < 1024) ? (int)n_chunks : 1024; // 8 chunks/CTA exact
        pe_tma_store_kernel<<<grid, 256>>>((float*)d_out, n_chunks);
    }
    if (rem_bytes > 0) {
        long long start_f = n_chunks * (CHUNK_BYTES / 4);
        long long rem_f = rem_bytes / 4;
        int blocks = (int)((rem_f + 255) / 256);
        pe_tail_kernel<<<blocks, 256>>>((float*)d_out, start_f, (long long)out_size);
    }
}

// round 12
// speedup vs baseline: 1.0285x; 1.0285x over previous
#include <cuda_runtime.h>
#include <math.h>

// FINAL: Output = 2*PE broadcast over batch. PE[pos][c], pos in [0,64),
// c in [0,16). Total out = 65536*64*16 fp32 = 256 MB of pure stores.
//
// R1-R11 conclusion: every store path (STG.128, STG.256, cp.async.bulk/TMA,
// dual-engine hybrids, L2-residency policy splits) lands in the same
// 45.1-47.3 us band; cutting DRAM writeback 20% changed wall time by zero.
// The limiter is the chip-level store stream (all 256 MB transits L2 once
// per launch at ~6.3 TB/s, DRAM writeback ~5 TB/s setting the replay
// period). This kernel is the simplest, most robust at-the-roofline writer:
// each thread computes its one float4 of the 1024-float-periodic pattern
// once, then grid-stride STG.128-streams it (~55 stores/thread, no loads,
// no smem, no sync, no drain tail).

__global__ void __launch_bounds__(256, 8)
pe_broadcast_kernel(float4* __restrict__ out, long long n4) {
    // blockDim.x == 256 and stride is a multiple of 256 float4s, so this
    // thread's (index % 256) is threadIdx.x forever -> compute value once.
    const int t = threadIdx.x;              // float4 index within 1024-float period
    const int pos = t >> 2;                 // sequence position 0..63
    const int c0  = (t & 3) * 4;            // first of 4 consecutive channels

    float4 v;
    {
        const float ln1e4_over8 = 1.1512925464970229f;  // ln(10000)/8
        float vals[4];
        #pragma unroll
        for (int k = 0; k < 4; ++k) {
            int c = c0 + k;
            float div = (float)pos * expf(-(float)c * ln1e4_over8);
            float s, co;
            sincosf(div, &s, &co);
            vals[k] = 2.0f * ((c & 1) == 0 ? s : co);
        }
        v.x = vals[0]; v.y = vals[1]; v.z = vals[2]; v.w = vals[3];
    }

    long long idx    = (long long)blockIdx.x * 256 + t;
    const long long stride = (long long)gridDim.x * 256;
    for (; idx < n4; idx += stride) {
        out[idx] = v;
    }
}

extern "C" void kernel_launch(void* const* d_in, const int* in_sizes, int n_in,
                              void* d_out, int out_size) {
    (void)d_in; (void)in_sizes; (void)n_in;
    long long n4 = (long long)out_size / 4;   // out_size = 65536*64*16, divisible by 4
    int blocks = 148 * 8;                     // persistent grid, ~55 STG.128/thread
    pe_broadcast_kernel<<<blocks, 256>>>((float4*)d_out, n4);
}

// round 13
// speedup vs baseline: 1.0328x; 1.0042x over previous
#include <cuda_runtime.h>
#include <math.h>

// FINAL: Output = 2*PE broadcast over batch. PE[pos][c], pos in [0,64),
// c in [0,16). Total out = 65536*64*16 fp32 = 256 MB of pure stores.
//
// R1-R12 conclusion: every store path (STG.128, STG.256, cp.async.bulk/TMA,
// dual-engine hybrids, L2-residency policy splits) lands in the same
// 45.1-47.3 us wall band with ncu kernel time pinned at 41.4-43.1 us;
// cutting DRAM writeback 20% (L2-resident split) changed wall time by zero.
// The limiter is the chip-level store stream: all 256 MB transits L2 once
// per launch at ~6.3 TB/s, with ~5 TB/s DRAM writeback setting the
// graph-replay steady-state period. This kernel is the simplest, most
// robust at-the-roofline writer: each thread computes its one float4 of
// the 1024-float-periodic pattern once, then grid-stride STG.128-streams
// it (~55 stores/thread, no loads, no smem, no sync, no drain tail).

__global__ void __launch_bounds__(256, 8)
pe_broadcast_kernel(float4* __restrict__ out, long long n4) {
    // blockDim.x == 256 and stride is a multiple of 256 float4s, so this
    // thread's (index % 256) is threadIdx.x forever -> compute value once.
    const int t = threadIdx.x;              // float4 index within 1024-float period
    const int pos = t >> 2;                 // sequence position 0..63
    const int c0  = (t & 3) * 4;            // first of 4 consecutive channels

    float4 v;
    {
        const float ln1e4_over8 = 1.1512925464970229f;  // ln(10000)/8
        float vals[4];
        #pragma unroll
        for (int k = 0; k < 4; ++k) {
            int c = c0 + k;
            float div = (float)pos * expf(-(float)c * ln1e4_over8);
            float s, co;
            sincosf(div, &s, &co);
            vals[k] = 2.0f * ((c & 1) == 0 ? s : co);
        }
        v.x = vals[0]; v.y = vals[1]; v.z = vals[2]; v.w = vals[3];
    }

    long long idx    = (long long)blockIdx.x * 256 + t;
    const long long stride = (long long)gridDim.x * 256;
    for (; idx < n4; idx += stride) {
        out[idx] = v;
    }
}

extern "C" void kernel_launch(void* const* d_in, const int* in_sizes, int n_in,
                              void* d_out, int out_size) {
    (void)d_in; (void)in_sizes; (void)n_in;
    long long n4 = (long long)out_size / 4;   // out_size = 65536*64*16, divisible by 4
    int blocks = 148 * 8;                     // persistent grid, ~55 STG.128/thread
    pe_broadcast_kernel<<<blocks, 256>>>((float4*)d_out, n4);
}

// round 14
// speedup vs baseline: 1.0811x; 1.0468x over previous
#include <cuda_runtime.h>
#include <math.h>

// Output = 2*PE broadcast over batch: 65536*64*16 fp32 = 256 MB pure stores.
//
// R1-R13: every store path (STG.128/STG.256/TMA-bulk/hybrids/L2-residency)
// lands in the same 45.1-47.3 us wall band, ncu kernel 41.4-43.1 us;
// reducing DRAM writeback 20% changed nothing. Limiter = chip store stream
// (256 MB through L2 once per launch @ ~6.3 TB/s; ~5 TB/s DRAM writeback
// sets the replay period). Last probe: double occupancy to 16 CTAs/SM so
// ~128 warps/SM keep every LTS write queue covered through the tail.

__global__ void __launch_bounds__(256, 16)
pe_broadcast_kernel(float4* __restrict__ out, long long n4) {
    // blockDim.x == 256 and stride is a multiple of 256 float4s, so this
    // thread's (index % 256) is threadIdx.x forever -> compute value once.
    const int t = threadIdx.x;              // float4 index within 1024-float period
    const int pos = t >> 2;                 // sequence position 0..63
    const int c0  = (t & 3) * 4;            // first of 4 consecutive channels

    float4 v;
    {
        const float ln1e4_over8 = 1.1512925464970229f;  // ln(10000)/8
        float vals[4];
        #pragma unroll
        for (int k = 0; k < 4; ++k) {
            int c = c0 + k;
            float div = (float)pos * expf(-(float)c * ln1e4_over8);
            float s, co;
            sincosf(div, &s, &co);
            vals[k] = 2.0f * ((c & 1) == 0 ? s : co);
        }
        v.x = vals[0]; v.y = vals[1]; v.z = vals[2]; v.w = vals[3];
    }

    long long idx    = (long long)blockIdx.x * 256 + t;
    const long long stride = (long long)gridDim.x * 256;
    for (; idx < n4; idx += stride) {
        out[idx] = v;
    }
}

extern "C" void kernel_launch(void* const* d_in, const int* in_sizes, int n_in,
                              void* d_out, int out_size) {
    (void)d_in; (void)in_sizes; (void)n_in;
    long long n4 = (long long)out_size / 4;   // 16,777,216 float4
    int blocks = 148 * 16;                    // 16 CTAs/SM, ~27 STG.128/thread
    pe_broadcast_kernel<<<blocks, 256>>>((float4*)d_out, n4);
}

// round 15
// speedup vs baseline: 1.1046x; 1.0217x over previous
#include <cuda_runtime.h>
#include <math.h>

// Output = 2*PE broadcast over batch: 65536*64*16 fp32 = 256 MB pure stores.
//
// R14 finding: kernel time is pinned (~41.5 us, chip store-stream limit) but
// wall/replay time tracks the ragged final wave. Oversubscribing the grid
// (2368 CTAs) cut wall 45.8 -> 43.8 us by letting queued CTAs refill SMs as
// early finishers retire. R15: extend to 4736 CTAs (4 refill waves,
// ~13 STG.128/thread) to further shrink the tail.

__global__ void __launch_bounds__(256, 8)
pe_broadcast_kernel(float4* __restrict__ out, long long n4) {
    // blockDim.x == 256 and stride is a multiple of 256 float4s, so this
    // thread's (index % 256) is threadIdx.x forever -> compute value once.
    const int t = threadIdx.x;              // float4 index within 1024-float period
    const int pos = t >> 2;                 // sequence position 0..63
    const int c0  = (t & 3) * 4;            // first of 4 consecutive channels

    float4 v;
    {
        const float ln1e4_over8 = 1.1512925464970229f;  // ln(10000)/8
        float vals[4];
        #pragma unroll
        for (int k = 0; k < 4; ++k) {
            int c = c0 + k;
            float div = (float)pos * expf(-(float)c * ln1e4_over8);
            float s, co;
            sincosf(div, &s, &co);
            vals[k] = 2.0f * ((c & 1) == 0 ? s : co);
        }
        v.x = vals[0]; v.y = vals[1]; v.z = vals[2]; v.w = vals[3];
    }

    long long idx    = (long long)blockIdx.x * 256 + t;
    const long long stride = (long long)gridDim.x * 256;
    for (; idx < n4; idx += stride) {
        out[idx] = v;
    }
}

extern "C" void kernel_launch(void* const* d_in, const int* in_sizes, int n_in,
                              void* d_out, int out_size) {
    (void)d_in; (void)in_sizes; (void)n_in;
    long long n4 = (long long)out_size / 4;   // 16,777,216 float4
    int blocks = 148 * 32;                    // 4736 CTAs: 4 refill waves,
                                              // ~13-14 STG.128 per thread
    pe_broadcast_kernel<<<blocks, 256>>>((float4*)d_out, n4);
}

// round 16
// speedup vs baseline: 1.1528x; 1.0436x over previous
#include <cuda_runtime.h>
#include <math.h>

// Output = 2*PE broadcast over batch: 65536*64*16 fp32 = 256 MB pure stores.
//
// R14/R15 finding: grid oversubscription monotonically improves BOTH the
// final-wave tail AND sustained store throughput (more live CTAs -> store
// streams spread across more LTS slices / DRAM banks at any instant):
//   1184 CTAs: 4908 GB/s, 45.8 us   |  2368: 5035 GB/s, 43.8 us
//   4736 CTAs: 5311 GB/s, 42.8 us   |  R16: 9472 CTAs, ~7 STG.128/thread.

__global__ void __launch_bounds__(256, 8)
pe_broadcast_kernel(float4* __restrict__ out, long long n4) {
    // blockDim.x == 256 and stride is a multiple of 256 float4s, so this
    // thread's (index % 256) is threadIdx.x forever -> compute value once.
    const int t = threadIdx.x;              // float4 index within 1024-float period
    const int pos = t >> 2;                 // sequence position 0..63
    const int c0  = (t & 3) * 4;            // first of 4 consecutive channels

    float4 v;
    {
        const float ln1e4_over8 = 1.1512925464970229f;  // ln(10000)/8
        float vals[4];
        #pragma unroll
        for (int k = 0; k < 4; ++k) {
            int c = c0 + k;
            float div = (float)pos * expf(-(float)c * ln1e4_over8);
            float s, co;
            sincosf(div, &s, &co);
            vals[k] = 2.0f * ((c & 1) == 0 ? s : co);
        }
        v.x = vals[0]; v.y = vals[1]; v.z = vals[2]; v.w = vals[3];
    }

    long long idx    = (long long)blockIdx.x * 256 + t;
    const long long stride = (long long)gridDim.x * 256;
    for (; idx < n4; idx += stride) {
        out[idx] = v;
    }
}

extern "C" void kernel_launch(void* const* d_in, const int* in_sizes, int n_in,
                              void* d_out, int out_size) {
    (void)d_in; (void)in_sizes; (void)n_in;
    long long n4 = (long long)out_size / 4;   // 16,777,216 float4
    int blocks = 148 * 64;                    // 9472 CTAs: ~7 STG.128/thread
    pe_broadcast_kernel<<<blocks, 256>>>((float4*)d_out, n4);
}